// round 8
// baseline (speedup 1.0000x reference)
#include <cuda_runtime.h>

#define N_TRIALS   8
#define T_MS       2500
#define N_NEURONS  16000
#define N_SAMPLES  50
#define K_MAX      160
#define N_BINS     20
#define SYNC_COST  10.0f
#define EPS_F      1e-7f
#define U_MAX      8000    // sum of all sample counts <= N_SAMPLES*K_MAX = 8000

// round(logspace(-3,0,20)*1000), matching numpy exactly
__constant__ int c_bins[N_BINS] = {1,1,2,3,4,6,9,13,18,26,38,55,78,113,162,234,336,483,695,1000};

// scratch (no allocations allowed -> __device__ globals)
__device__ int   g_U[N_TRIALS * U_MAX];            // per-trial sorted union of active neurons
__device__ int   g_lenU[N_TRIALS];
__device__ int   g_slist[N_TRIALS * 64];           // sample ids per trial
__device__ int   g_scount[N_TRIALS];
__device__ int   g_P[N_SAMPLES * K_MAX];           // position of idx[s][k] within its trial union
__device__ float g_sel[N_SAMPLES * T_MS];          // 500 KB
__device__ float g_fano_parts[N_BINS * N_SAMPLES];

// ---------------------------------------------------------------------------
// Kernel A: per trial r, build sorted union U_r of all neurons used by its
// samples, plus per-sample compact positions P[s][k]. One block per trial.
// Deterministic flag + block scan (no atomics).
// ---------------------------------------------------------------------------
__global__ void __launch_bounds__(512) prep_kernel(const int* __restrict__ trials,
                                                   const int* __restrict__ idx,
                                                   const int* __restrict__ counts)
{
    const int r   = blockIdx.x;
    const int tid = threadIdx.x;

    __shared__ short sm[N_NEURONS];   // flag, then position map (32 KB)
    __shared__ int   bsum[512];
    __shared__ int   slist_s[52];
    __shared__ int   scount_s;

    for (int n = tid; n < N_NEURONS; n += 512) sm[n] = 0;
    if (tid == 0) {
        int c = 0;
        for (int s = 0; s < N_SAMPLES; s++)
            if (trials[s] == r) slist_s[c++] = s;
        scount_s = c;
    }
    __syncthreads();

    const int sc = scount_s;

    // flag all active neurons of this trial's samples (benign same-value races)
    for (int p = tid; p < sc * K_MAX; p += 512) {
        const int si = p / K_MAX, k = p % K_MAX;
        const int s  = slist_s[si];
        if (k < counts[s]) sm[idx[s * K_MAX + k]] = 1;
    }
    __syncthreads();

    // per-thread chunk sums (chunk = 32: 512*32 = 16384 >= 16000)
    const int base = tid * 32;
    int loc = 0;
    #pragma unroll
    for (int i = 0; i < 32; i++) {
        const int n = base + i;
        if (n < N_NEURONS) loc += sm[n];
    }
    bsum[tid] = loc;
    __syncthreads();

    // Hillis-Steele inclusive scan over 512 (deterministic)
    for (int off = 1; off < 512; off <<= 1) {
        const int v   = bsum[tid];
        const int add = (tid >= off) ? bsum[tid - off] : 0;
        __syncthreads();
        bsum[tid] = v + add;
        __syncthreads();
    }
    const int excl = (tid == 0) ? 0 : bsum[tid - 1];

    // pass 2: assign positions, emit union entries (ascending neuron order)
    int pos = excl;
    #pragma unroll
    for (int i = 0; i < 32; i++) {
        const int n = base + i;
        if (n < N_NEURONS) {
            const short f = sm[n];
            sm[n] = (short)pos;           // position map (valid where flagged)
            if (f) { g_U[r * U_MAX + pos] = n; pos++; }
        }
    }
    __syncthreads();

    if (tid == 511) g_lenU[r] = pos;      // = total union size
    if (tid == 0)   g_scount[r] = sc;
    if (tid < sc)   g_slist[r * 64 + tid] = slist_s[tid];

    // per-sample compact positions
    for (int p = tid; p < sc * K_MAX; p += 512) {
        const int si = p / K_MAX, k = p % K_MAX;
        const int s  = slist_s[si];
        if (k < counts[s])
            g_P[s * K_MAX + k] = (int)sm[idx[s * K_MAX + k]];
    }
}

// ---------------------------------------------------------------------------
// Kernel B: one block per (t, trial). Gather the trial's union values for
// this t into smem ONCE (each DRAM line fetched exactly once per (r,t) by
// construction), then each warp computes its samples' sums from smem.
// ---------------------------------------------------------------------------
__global__ void __launch_bounds__(256) gather_sel_kernel(const float* __restrict__ spikes,
                                                         const int*   __restrict__ counts)
{
    const int t = blockIdx.x;
    const int r = blockIdx.y;

    __shared__ float vals[U_MAX];   // 32 KB

    const int len = g_lenU[r];
    const int sc  = g_scount[r];
    if (sc == 0) return;

    const float* __restrict__ row =
        spikes + ((long long)r * T_MS + t) * (long long)N_NEURONS;
    const int* __restrict__ Ur = g_U + r * U_MAX;

    // ascending-address gather, consecutive threads -> nearby addresses
    for (int j = threadIdx.x; j < len; j += 256)
        vals[j] = row[Ur[j]];
    __syncthreads();

    const int wid  = threadIdx.x >> 5;
    const int lane = threadIdx.x & 31;

    for (int si = wid; si < sc; si += 8) {
        const int s   = g_slist[r * 64 + si];
        const int cnt = counts[s];
        const int* __restrict__ Ps = g_P + s * K_MAX;

        float v = 0.f;
        for (int k = lane; k < cnt; k += 32)
            v += vals[Ps[k]];

        // warp tree reduce (values are exact small integers -> exact)
        #pragma unroll
        for (int off = 16; off > 0; off >>= 1)
            v += __shfl_down_sync(0xFFFFFFFFu, v, off);

        if (lane == 0) g_sel[s * T_MS + t] = v;
    }
}

// ---------------------------------------------------------------------------
// Kernel C (fused over bins): one block per sample. Two-pass variance,
// deterministic tree reductions.
// ---------------------------------------------------------------------------
__global__ void __launch_bounds__(256) fano_kernel()
{
    const int s   = blockIdx.x;
    const int tid = threadIdx.x;

    __shared__ float row[T_MS];
    __shared__ float binsum[T_MS];
    __shared__ float red[256];

    for (int t = tid; t < T_MS; t += blockDim.x)
        row[t] = g_sel[s * T_MS + t];
    __syncthreads();

    for (int b = 0; b < N_BINS; b++) {
        const int bs = c_bins[b];
        const int nb = T_MS / bs;

        for (int j = tid; j < nb; j += blockDim.x) {
            const int base = j * bs;
            float b0=0.f, b1=0.f, b2=0.f, b3=0.f;
            int i = 0;
            for (; i + 4 <= bs; i += 4) {
                b0 += row[base + i + 0];
                b1 += row[base + i + 1];
                b2 += row[base + i + 2];
                b3 += row[base + i + 3];
            }
            float acc = (b0+b1)+(b2+b3);
            for (; i < bs; i++) acc += row[base + i];
            binsum[j] = acc;
        }
        __syncthreads();

        float part = 0.f;
        for (int j = tid; j < nb; j += blockDim.x) part += binsum[j];
        red[tid] = part;
        __syncthreads();
        #pragma unroll
        for (int off = 128; off > 0; off >>= 1) {
            if (tid < off) red[tid] += red[tid + off];
            __syncthreads();
        }
        const float mean = red[0] / (float)nb;
        __syncthreads();

        float part2 = 0.f;
        for (int j = tid; j < nb; j += blockDim.x) {
            const float d = binsum[j] - mean;
            part2 += d * d;
        }
        red[tid] = part2;
        __syncthreads();
        #pragma unroll
        for (int off = 128; off > 0; off >>= 1) {
            if (tid < off) red[tid] += red[tid + off];
            __syncthreads();
        }
        if (tid == 0) {
            const float var = red[0] / (float)nb;
            g_fano_parts[b * N_SAMPLES + s] = var / fmaxf(mean, EPS_F);
        }
        __syncthreads();
    }
}

// ---------------------------------------------------------------------------
// Kernel D: parallel loss. 20 warps, warp b reduces its 50 sample fanos.
// ---------------------------------------------------------------------------
__global__ void __launch_bounds__(640) loss_kernel(const float* __restrict__ exp_fanos,
                                                   float* __restrict__ out)
{
    const int w    = threadIdx.x >> 5;   // bin
    const int lane = threadIdx.x & 31;

    __shared__ float sq[N_BINS];

    float v = 0.f;
    if (lane < N_SAMPLES)      v += g_fano_parts[w * N_SAMPLES + lane];
    if (lane + 32 < N_SAMPLES) v += g_fano_parts[w * N_SAMPLES + lane + 32];
    #pragma unroll
    for (int off = 16; off > 0; off >>= 1)
        v += __shfl_down_sync(0xFFFFFFFFu, v, off);
    if (lane == 0) {
        const float fano = v / (float)N_SAMPLES;
        const float d = exp_fanos[w] - fano;
        sq[w] = d * d;
    }
    __syncthreads();

    if (w == 0) {
        float x = (lane < N_BINS) ? sq[lane] : 0.f;
        #pragma unroll
        for (int off = 16; off > 0; off >>= 1)
            x += __shfl_down_sync(0xFFFFFFFFu, x, off);
        if (lane == 0) out[0] = SYNC_COST * (x / (float)N_BINS);
    }
}

// ---------------------------------------------------------------------------
extern "C" void kernel_launch(void* const* d_in, const int* in_sizes, int n_in,
                              void* d_out, int out_size)
{
    const float* spikes    = (const float*)d_in[0];
    const float* exp_fanos = (const float*)d_in[1];
    const int*   trials    = (const int*)  d_in[2];
    const int*   idx       = (const int*)  d_in[3];
    const int*   counts    = (const int*)  d_in[4];
    float*       out       = (float*)d_out;

    prep_kernel<<<N_TRIALS, 512>>>(trials, idx, counts);

    dim3 gB(T_MS, N_TRIALS);
    gather_sel_kernel<<<gB, 256>>>(spikes, counts);

    fano_kernel<<<N_SAMPLES, 256>>>();

    loss_kernel<<<1, 640>>>(exp_fanos, out);
}

// round 9
// speedup vs baseline: 1.0575x; 1.0575x over previous
#include <cuda_runtime.h>

#define N_TRIALS   8
#define T_MS       2500
#define N_NEURONS  16000
#define N_SAMPLES  50
#define K_MAX      160
#define N_BINS     20
#define SYNC_COST  10.0f
#define EPS_F      1e-7f
#define U_MAX      8000     // per-trial union cap (sum of all counts <= 8000)
#define U_SUM_MAX  8000     // global flattened union cap
#define TT         10       // time-steps per gather thread
#define T_CH       (T_MS / TT)   // 250

// round(logspace(-3,0,20)*1000), matching numpy exactly
__constant__ int c_bins[N_BINS] = {1,1,2,3,4,6,9,13,18,26,38,55,78,113,162,234,336,483,695,1000};

// scratch (no allocations allowed -> __device__ globals)
__device__ int   g_U[N_TRIALS * U_MAX];      // per-trial sorted union (neuron ids)
__device__ int   g_lenU[N_TRIALS];
__device__ int   g_off[N_TRIALS];            // exclusive prefix of lenU
__device__ int   g_totalU;
__device__ int   g_src[U_SUM_MAX];           // flattened: element offset r*T*N + n
__device__ int   g_P[N_SAMPLES * K_MAX];     // per-sample local position in its trial union
__device__ float g_compact[T_MS * U_SUM_MAX]; // 80 MB staging: [t][g]
__device__ float g_sel[N_SAMPLES * T_MS];
__device__ float g_fano_parts[N_BINS * N_SAMPLES];

// ---------------------------------------------------------------------------
// Kernel A: per trial r, sorted union + per-sample local positions.
// One block per trial; deterministic flag + block scan.
// ---------------------------------------------------------------------------
__global__ void __launch_bounds__(512) prep_kernel(const int* __restrict__ trials,
                                                   const int* __restrict__ idx,
                                                   const int* __restrict__ counts)
{
    const int r   = blockIdx.x;
    const int tid = threadIdx.x;

    __shared__ short sm[N_NEURONS];   // flag, then position map (32 KB)
    __shared__ int   bsum[512];
    __shared__ int   slist_s[52];
    __shared__ int   scount_s;

    for (int n = tid; n < N_NEURONS; n += 512) sm[n] = 0;
    if (tid == 0) {
        int c = 0;
        for (int s = 0; s < N_SAMPLES; s++)
            if (trials[s] == r) slist_s[c++] = s;
        scount_s = c;
    }
    __syncthreads();

    const int sc = scount_s;

    for (int p = tid; p < sc * K_MAX; p += 512) {
        const int si = p / K_MAX, k = p % K_MAX;
        const int s  = slist_s[si];
        if (k < counts[s]) sm[idx[s * K_MAX + k]] = 1;
    }
    __syncthreads();

    const int base = tid * 32;   // 512*32 = 16384 >= 16000
    int loc = 0;
    #pragma unroll
    for (int i = 0; i < 32; i++) {
        const int n = base + i;
        if (n < N_NEURONS) loc += sm[n];
    }
    bsum[tid] = loc;
    __syncthreads();

    for (int off = 1; off < 512; off <<= 1) {
        const int v   = bsum[tid];
        const int add = (tid >= off) ? bsum[tid - off] : 0;
        __syncthreads();
        bsum[tid] = v + add;
        __syncthreads();
    }
    const int excl = (tid == 0) ? 0 : bsum[tid - 1];

    int pos = excl;
    #pragma unroll
    for (int i = 0; i < 32; i++) {
        const int n = base + i;
        if (n < N_NEURONS) {
            const short f = sm[n];
            sm[n] = (short)pos;
            if (f) { g_U[r * U_MAX + pos] = n; pos++; }
        }
    }
    __syncthreads();

    if (tid == 511) g_lenU[r] = pos;

    for (int p = tid; p < sc * K_MAX; p += 512) {
        const int si = p / K_MAX, k = p % K_MAX;
        const int s  = slist_s[si];
        if (k < counts[s])
            g_P[s * K_MAX + k] = (int)sm[idx[s * K_MAX + k]];
    }
}

// ---------------------------------------------------------------------------
// Kernel A2: flatten unions across trials into g_src (1 block).
// ---------------------------------------------------------------------------
__global__ void __launch_bounds__(512) flatten_kernel()
{
    const int tid = threadIdx.x;
    __shared__ int soff[N_TRIALS + 1];

    if (tid == 0) {
        int acc = 0;
        for (int r = 0; r < N_TRIALS; r++) {
            soff[r] = acc;
            g_off[r] = acc;
            acc += g_lenU[r];
        }
        soff[N_TRIALS] = acc;
        g_totalU = acc;
    }
    __syncthreads();

    for (int r = 0; r < N_TRIALS; r++) {
        const int len = soff[r + 1] - soff[r];
        const int rb  = r * (T_MS * N_NEURONS);
        for (int j = tid; j < len; j += 512)
            g_src[soff[r] + j] = rb + g_U[r * U_MAX + j];
    }
}

// ---------------------------------------------------------------------------
// Kernel B: pure streaming dedup gather. compact[t][g] = spikes[src[g] + t*N].
// No barriers / smem / reduce -> DRAM stream never starves.
// grid (ceil(U_SUM_MAX/256), T_CH), block 256; TT time-steps per thread.
// ---------------------------------------------------------------------------
__global__ void __launch_bounds__(256) gather_kernel(const float* __restrict__ spikes)
{
    const int g = blockIdx.x * 256 + threadIdx.x;
    if (g >= g_totalU) return;

    const int t0  = blockIdx.y * TT;
    const int src = g_src[g];

    float v[TT];
    #pragma unroll
    for (int i = 0; i < TT; i++)
        v[i] = spikes[(long long)src + (long long)(t0 + i) * N_NEURONS];

    #pragma unroll
    for (int i = 0; i < TT; i++)
        g_compact[(t0 + i) * U_SUM_MAX + g] = v[i];
}

// ---------------------------------------------------------------------------
// Kernel C: block per t. Stage compact row (coalesced) to smem; 8 warps sweep
// the 50 samples. Deterministic warp tree reduce of exact 0/1-integer sums.
// ---------------------------------------------------------------------------
__global__ void __launch_bounds__(256) reduce_kernel(const int* __restrict__ trials,
                                                     const int* __restrict__ counts)
{
    const int t   = blockIdx.x;
    const int tid = threadIdx.x;

    __shared__ float vals[U_SUM_MAX];   // 32 KB worst case

    const int totalU = g_totalU;
    for (int j = tid; j < totalU; j += 256)
        vals[j] = g_compact[t * U_SUM_MAX + j];
    __syncthreads();

    const int wid  = tid >> 5;
    const int lane = tid & 31;

    for (int s = wid; s < N_SAMPLES; s += 8) {
        const int cnt = counts[s];
        const int off = g_off[trials[s]];
        const int* __restrict__ Ps = g_P + s * K_MAX;

        float v = 0.f;
        for (int k = lane; k < cnt; k += 32)
            v += vals[off + Ps[k]];

        #pragma unroll
        for (int o = 16; o > 0; o >>= 1)
            v += __shfl_down_sync(0xFFFFFFFFu, v, o);

        if (lane == 0) g_sel[s * T_MS + t] = v;
    }
}

// ---------------------------------------------------------------------------
// Kernel D (fused over bins): one block per sample. Two-pass variance,
// deterministic tree reductions.
// ---------------------------------------------------------------------------
__global__ void __launch_bounds__(256) fano_kernel()
{
    const int s   = blockIdx.x;
    const int tid = threadIdx.x;

    __shared__ float row[T_MS];
    __shared__ float binsum[T_MS];
    __shared__ float red[256];

    for (int t = tid; t < T_MS; t += blockDim.x)
        row[t] = g_sel[s * T_MS + t];
    __syncthreads();

    for (int b = 0; b < N_BINS; b++) {
        const int bs = c_bins[b];
        const int nb = T_MS / bs;

        for (int j = tid; j < nb; j += blockDim.x) {
            const int base = j * bs;
            float b0=0.f, b1=0.f, b2=0.f, b3=0.f;
            int i = 0;
            for (; i + 4 <= bs; i += 4) {
                b0 += row[base + i + 0];
                b1 += row[base + i + 1];
                b2 += row[base + i + 2];
                b3 += row[base + i + 3];
            }
            float acc = (b0+b1)+(b2+b3);
            for (; i < bs; i++) acc += row[base + i];
            binsum[j] = acc;
        }
        __syncthreads();

        float part = 0.f;
        for (int j = tid; j < nb; j += blockDim.x) part += binsum[j];
        red[tid] = part;
        __syncthreads();
        #pragma unroll
        for (int off = 128; off > 0; off >>= 1) {
            if (tid < off) red[tid] += red[tid + off];
            __syncthreads();
        }
        const float mean = red[0] / (float)nb;
        __syncthreads();

        float part2 = 0.f;
        for (int j = tid; j < nb; j += blockDim.x) {
            const float d = binsum[j] - mean;
            part2 += d * d;
        }
        red[tid] = part2;
        __syncthreads();
        #pragma unroll
        for (int off = 128; off > 0; off >>= 1) {
            if (tid < off) red[tid] += red[tid + off];
            __syncthreads();
        }
        if (tid == 0) {
            const float var = red[0] / (float)nb;
            g_fano_parts[b * N_SAMPLES + s] = var / fmaxf(mean, EPS_F);
        }
        __syncthreads();
    }
}

// ---------------------------------------------------------------------------
// Kernel E: parallel loss. 20 warps, warp b reduces its 50 sample fanos.
// ---------------------------------------------------------------------------
__global__ void __launch_bounds__(640) loss_kernel(const float* __restrict__ exp_fanos,
                                                   float* __restrict__ out)
{
    const int w    = threadIdx.x >> 5;
    const int lane = threadIdx.x & 31;

    __shared__ float sq[N_BINS];

    float v = 0.f;
    if (lane < N_SAMPLES)      v += g_fano_parts[w * N_SAMPLES + lane];
    if (lane + 32 < N_SAMPLES) v += g_fano_parts[w * N_SAMPLES + lane + 32];
    #pragma unroll
    for (int off = 16; off > 0; off >>= 1)
        v += __shfl_down_sync(0xFFFFFFFFu, v, off);
    if (lane == 0) {
        const float fano = v / (float)N_SAMPLES;
        const float d = exp_fanos[w] - fano;
        sq[w] = d * d;
    }
    __syncthreads();

    if (w == 0) {
        float x = (lane < N_BINS) ? sq[lane] : 0.f;
        #pragma unroll
        for (int off = 16; off > 0; off >>= 1)
            x += __shfl_down_sync(0xFFFFFFFFu, x, off);
        if (lane == 0) out[0] = SYNC_COST * (x / (float)N_BINS);
    }
}

// ---------------------------------------------------------------------------
extern "C" void kernel_launch(void* const* d_in, const int* in_sizes, int n_in,
                              void* d_out, int out_size)
{
    const float* spikes    = (const float*)d_in[0];
    const float* exp_fanos = (const float*)d_in[1];
    const int*   trials    = (const int*)  d_in[2];
    const int*   idx       = (const int*)  d_in[3];
    const int*   counts    = (const int*)  d_in[4];
    float*       out       = (float*)d_out;

    prep_kernel<<<N_TRIALS, 512>>>(trials, idx, counts);
    flatten_kernel<<<1, 512>>>();

    dim3 gB((U_SUM_MAX + 255) / 256, T_CH);
    gather_kernel<<<gB, 256>>>(spikes);

    reduce_kernel<<<T_MS, 256>>>(trials, counts);

    fano_kernel<<<N_SAMPLES, 256>>>();

    loss_kernel<<<1, 640>>>(exp_fanos, out);
}